// round 16
// baseline (speedup 1.0000x reference)
#include <cuda_runtime.h>
#include <cuda_fp16.h>
#include <cstddef>

#define Bsz  1024
#define Tsz  128
#define Isz  128
#define Hsz  256
#define G3   768
#define Ksz  8
#define E1sz 512
#define E2sz 256
#define MT   (Bsz * Tsz)

typedef unsigned long long u64;
typedef unsigned int u32;

__device__ __forceinline__ float sigmoidf_(float x){ return __fdividef(1.0f, 1.0f + __expf(-x)); }
__device__ __forceinline__ float tanhf_(float x){ return 1.0f - __fdividef(2.0f, __expf(2.0f*x) + 1.0f); }

__device__ __forceinline__ u32 smem_u32(const void* p){
    u32 a; asm("{ .reg .u64 t; cvta.to.shared.u64 t, %1; cvt.u32.u64 %0, t; }" : "=r"(a) : "l"(p)); return a;
}
__device__ __forceinline__ void ldmA(u32 a, u32& r0, u32& r1, u32& r2, u32& r3){
    asm volatile("ldmatrix.sync.aligned.m8n8.x4.shared.b16 {%0,%1,%2,%3},[%4];"
                 : "=r"(r0),"=r"(r1),"=r"(r2),"=r"(r3) : "r"(a));
}
__device__ __forceinline__ void ldmB(u32 a, u32& r0, u32& r1){
    asm volatile("ldmatrix.sync.aligned.m8n8.x2.shared.b16 {%0,%1},[%2];"
                 : "=r"(r0),"=r"(r1) : "r"(a));
}
__device__ __forceinline__ void mma16816(float* d, u32 a0,u32 a1,u32 a2,u32 a3,u32 b0,u32 b1){
    asm volatile("mma.sync.aligned.m16n8k16.row.col.f32.f16.f16.f32 "
                 "{%0,%1,%2,%3},{%4,%5,%6,%7},{%8,%9},{%0,%1,%2,%3};"
                 : "+f"(d[0]),"+f"(d[1]),"+f"(d[2]),"+f"(d[3])
                 : "r"(a0),"r"(a1),"r"(a2),"r"(a3),"r"(b0),"r"(b1));
}
#define SWZ(row, c) ((u32)((((c) ^ ((row) & 7)) << 4)))

// ---------------- scratch ----------------
__device__ float g_gi0[(size_t)Tsz * Bsz * G3];
__device__ float g_gi1[(size_t)Tsz * Bsz * G3];
__device__ __half g_xH[(size_t)MT * Isz];
__device__ __half g_WihH0[2][(size_t)G3 * Isz];
__device__ __half g_WhhH0[2][(size_t)G3 * Hsz];
__device__ __half g_WihH1[2][(size_t)G3 * Hsz];
__device__ __half g_WhhH1[2][(size_t)G3 * Hsz];
__device__ __half g_hAll[(size_t)Tsz * Bsz * Hsz];     // L0 h, all t (64MB)
__device__ __half g_hH1[2][(size_t)Bsz * Hsz];         // L1 ping-pong
__device__ __half g_eW1H[2][(size_t)Ksz * E1sz * Hsz];
__device__ __half g_eW2H[2][(size_t)Ksz * E2sz * E1sz];
__device__ __half g_e1H[(size_t)Ksz * Bsz * E1sz];
__device__ float g_z[(size_t)Bsz * Hsz];
__device__ float g_q[Bsz * Ksz];
__device__ float g_e2[(size_t)Ksz * Bsz * E2sz];
__device__ unsigned g_cnt0[128], g_gen0[128], g_cnt1[128], g_gen1[128];

__device__ __forceinline__ void grid_bar(unsigned* cnt, volatile unsigned* gen,
                                         unsigned target, unsigned nCTAm1){
    __syncthreads();
    if (threadIdx.x == 0){
        __threadfence();
        if (atomicAdd(cnt, 1u) == nCTAm1){
            atomicExch(cnt, 0u); __threadfence(); *gen = target;
        } else { while (*gen < target) { } }
        __threadfence();
    }
    __syncthreads();
}

__global__ void __launch_bounds__(256) cvt_split(
    const float* __restrict__ in, __half* __restrict__ hi,
    __half* __restrict__ lo, int n)
{
    int i = blockIdx.x * 256 + threadIdx.x;
    if (i < n){
        float v = in[i];
        __half h = __float2half_rn(v);
        hi[i] = h;
        lo[i] = __float2half_rn(v - __half2float(h));
    }
}
__global__ void __launch_bounds__(256) cvt_h(
    const float* __restrict__ in, __half* __restrict__ out, int n)
{
    int i = blockIdx.x * 256 + threadIdx.x;
    if (i < n) out[i] = __float2half_rn(in[i]);
}

// ---------------------------------------------------------------------------
// mma_multi (proven)
// ---------------------------------------------------------------------------
template<int NOPS, int KK, int RS, int F>
__device__ __forceinline__ void mma_multi(
    char* Asm,
    char* B0, float (&o0)[2][F][4], char* B1, float (&o1)[2][F][4],
    char* B2, float (&o2)[2][F][4], char* B3, float (&o3)[2][F][4],
    int lane, int wM, int wN)
{
    u32 aB = smem_u32(Asm);
    u32 bA0 = smem_u32(B0);
    u32 bA1 = (NOPS > 1) ? smem_u32(B1) : 0;
    u32 bA2 = (NOPS > 2) ? smem_u32(B2) : 0;
    u32 bA3 = (NOPS > 3) ? smem_u32(B3) : 0;
    const int ar0 = wM*32 + (lane & 15), ar1 = ar0 + 16;
    const int ah = lane >> 4;
    const int br = wN*(8*F) + (lane & 7);
    const int bh = (lane >> 3) & 1;
    #pragma unroll
    for (int kk = 0; kk < KK; kk++){
        int ac = kk*2 + ah, bc = kk*2 + bh;
        u32 x0,x1,x2,x3, y0,y1,y2,y3;
        ldmA(aB + (u32)(ar0*RS) + SWZ(ar0, ac), x0,x1,x2,x3);
        ldmA(aB + (u32)(ar1*RS) + SWZ(ar1, ac), y0,y1,y2,y3);
        #pragma unroll
        for (int f = 0; f < F; f++){
            int brr = br + f*8;
            u32 b0,b1;
            ldmB(bA0 + (u32)(brr*RS) + SWZ(brr, bc), b0,b1);
            mma16816(o0[0][f], x0,x1,x2,x3, b0,b1);
            mma16816(o0[1][f], y0,y1,y2,y3, b0,b1);
            if (NOPS > 1){
                ldmB(bA1 + (u32)(brr*RS) + SWZ(brr, bc), b0,b1);
                mma16816(o1[0][f], x0,x1,x2,x3, b0,b1);
                mma16816(o1[1][f], y0,y1,y2,y3, b0,b1);
            }
            if (NOPS > 2){
                ldmB(bA2 + (u32)(brr*RS) + SWZ(brr, bc), b0,b1);
                mma16816(o2[0][f], x0,x1,x2,x3, b0,b1);
                mma16816(o2[1][f], y0,y1,y2,y3, b0,b1);
            }
            if (NOPS > 3){
                ldmB(bA3 + (u32)(brr*RS) + SWZ(brr, bc), b0,b1);
                mma16816(o3[0][f], x0,x1,x2,x3, b0,b1);
                mma16816(o3[1][f], y0,y1,y2,y3, b0,b1);
            }
        }
    }
}

__device__ __forceinline__ void fill_A(char* Asm, const __half* src, int m0, int tid){
    #pragma unroll
    for (int i = 0; i < 8; i++){
        int id = tid + i*256, row = id >> 5, c = id & 31;
        uint4 v = __ldcg(reinterpret_cast<const uint4*>(src + (size_t)(m0+row)*Hsz) + c);
        *reinterpret_cast<uint4*>(Asm + (size_t)row*512 + SWZ(row, c)) = v;
    }
}
__device__ __forceinline__ void fill_Bg(char* dst, const __half* W, int n0, int tid){
    for (int i = tid; i < 96*32; i += 256){
        int j = i >> 5, c = i & 31;
        int wrow = ((j >> 3) % 3)*Hsz + n0 + (j/24)*8 + (j & 7);
        uint4 v = *(reinterpret_cast<const uint4*>(W + (size_t)wrow*Hsz) + c);
        *reinterpret_cast<uint4*>(dst + (size_t)j*512 + SWZ(j, c)) = v;
    }
}
template<int F>
__device__ __forceinline__ void zero_acc(float (&a)[2][F][4]){
    #pragma unroll
    for (int m = 0; m < 2; m++)
        #pragma unroll
        for (int f = 0; f < F; f++)
            #pragma unroll
            for (int q = 0; q < 4; q++) a[m][f][q] = 0.0f;
}
__device__ __forceinline__ void store_nat(float* ghsm, float acc[2][3][4], int lane, int wM, int wN){
    #pragma unroll
    for (int m = 0; m < 2; m++)
        #pragma unroll
        for (int f = 0; f < 3; f++){
            int r0 = wM*32 + m*16 + (lane >> 2);
            int j0 = wN*24 + f*8 + 2*(lane & 3);
            int n0c = (j0 % 3)*32 + j0/3;
            int n1c = ((j0+1) % 3)*32 + (j0+1)/3;
            ghsm[r0*96 + n0c]     = acc[m][f][0];
            ghsm[r0*96 + n1c]     = acc[m][f][1];
            ghsm[(r0+8)*96 + n0c] = acc[m][f][2];
            ghsm[(r0+8)*96 + n1c] = acc[m][f][3];
        }
}

// ---------------------------------------------------------------------------
// gi0 = x @ Wih0^T : fp16 2-pass, K=128 (proven R15)
// ---------------------------------------------------------------------------
__global__ void __launch_bounds__(256) gi0_mma(
    const __half* __restrict__ xH,
    const __half* __restrict__ wHi, const __half* __restrict__ wLo,
    float* __restrict__ gi0)
{
    extern __shared__ char smc[];
    char* Bhi = smc;
    char* Blo = smc + 24*1024;
    char* Asm = smc + 48*1024;
    float* ghsm = reinterpret_cast<float*>(smc);

    const int tid = threadIdx.x, lane = tid & 31, w = tid >> 5;
    const int wM = w >> 2, wN = w & 3;
    const int n0 = blockIdx.x * 32, m0 = blockIdx.y * 64;
    const size_t PG = (size_t)Bsz * G3;

    for (int i = tid; i < 96*16; i += 256){
        int j = i >> 4, c = i & 15;
        int wrow = (j % 3)*Hsz + n0 + (j/3);
        *reinterpret_cast<uint4*>(Bhi + (size_t)j*256 + SWZ(j, c)) =
            *(reinterpret_cast<const uint4*>(wHi + (size_t)wrow*Isz) + c);
        *reinterpret_cast<uint4*>(Blo + (size_t)j*256 + SWZ(j, c)) =
            *(reinterpret_cast<const uint4*>(wLo + (size_t)wrow*Isz) + c);
    }
    #pragma unroll
    for (int i = 0; i < 4; i++){
        int id = tid + i*256, row = id >> 4, c = id & 15;
        *reinterpret_cast<uint4*>(Asm + (size_t)row*256 + SWZ(row, c)) =
            *(reinterpret_cast<const uint4*>(xH + (size_t)(m0+row)*Isz) + c);
    }
    __syncthreads();

    float acc[2][3][4];
    zero_acc(acc);
    mma_multi<2, 8, 256, 3>(Asm, Bhi, acc, Blo, acc, Bhi, acc, Bhi, acc, lane, wM, wN);
    __syncthreads();
    store_nat(ghsm, acc, lane, wM, wN);
    __syncthreads();

    const int b = m0 >> 7, t0 = m0 & 127;
    #pragma unroll
    for (int i = 0; i < 6; i++){
        int fid = tid + i*256;
        int row = fid / 24, cq = fid % 24;
        int g = cq >> 3, hc4 = (cq & 7)*4;
        float4 v = *reinterpret_cast<const float4*>(ghsm + row*96 + g*32 + hc4);
        *reinterpret_cast<float4*>(gi0 + (size_t)(t0+row)*PG + (size_t)b*G3 + g*256 + n0 + hc4) = v;
    }
}

// ---------------------------------------------------------------------------
// gi1 = hAll @ Wih1^T : fp16 2-pass, K=256. m = b*128 + t; A row (b,t) at
// hAll + t*PHB + b*Hsz. Grid (8, 2048), smem 128KB.
// ---------------------------------------------------------------------------
__global__ void __launch_bounds__(256) gi1_mma(
    const __half* __restrict__ hAll,
    const __half* __restrict__ wHi, const __half* __restrict__ wLo,
    float* __restrict__ gi1)
{
    extern __shared__ char smc[];
    char* Bhi = smc;                  // 48KB
    char* Blo = smc + 48*1024;        // 48KB
    char* Asm = smc + 96*1024;        // 32KB
    float* ghsm = reinterpret_cast<float*>(smc);

    const int tid = threadIdx.x, lane = tid & 31, w = tid >> 5;
    const int wM = w >> 2, wN = w & 3;
    const int n0 = blockIdx.x * 32, m0 = blockIdx.y * 64;
    const size_t PG = (size_t)Bsz * G3, PHB = (size_t)Bsz * Hsz;
    const int b = m0 >> 7, t0 = m0 & 127;

    for (int i = tid; i < 96*32; i += 256){
        int j = i >> 5, c = i & 31;
        int wrow = (j % 3)*Hsz + n0 + (j/3);
        *reinterpret_cast<uint4*>(Bhi + (size_t)j*512 + SWZ(j, c)) =
            *(reinterpret_cast<const uint4*>(wHi + (size_t)wrow*Hsz) + c);
        *reinterpret_cast<uint4*>(Blo + (size_t)j*512 + SWZ(j, c)) =
            *(reinterpret_cast<const uint4*>(wLo + (size_t)wrow*Hsz) + c);
    }
    #pragma unroll
    for (int i = 0; i < 8; i++){
        int id = tid + i*256, row = id >> 5, c = id & 31;
        const __half* src = hAll + (size_t)(t0 + row)*PHB + (size_t)b*Hsz;
        *reinterpret_cast<uint4*>(Asm + (size_t)row*512 + SWZ(row, c)) =
            *(reinterpret_cast<const uint4*>(src) + c);
    }
    __syncthreads();

    float acc[2][3][4];
    zero_acc(acc);
    mma_multi<2, 16, 512, 3>(Asm, Bhi, acc, Blo, acc, Bhi, acc, Bhi, acc, lane, wM, wN);
    __syncthreads();
    store_nat(ghsm, acc, lane, wM, wN);
    __syncthreads();

    #pragma unroll
    for (int i = 0; i < 6; i++){
        int fid = tid + i*256;
        int row = fid / 24, cq = fid % 24;
        int g = cq >> 3, hc4 = (cq & 7)*4;
        float4 v = *reinterpret_cast<const float4*>(ghsm + row*96 + g*32 + hc4);
        *reinterpret_cast<float4*>(gi1 + (size_t)(t0+row)*PG + (size_t)b*G3 + g*256 + n0 + hc4) = v;
    }
}

// ---------------------------------------------------------------------------
// Persistent HMMA GRU chain, fp16 2-pass (no gi1 fusion).
// ALLT: store h plane per t (layer 0); else ping-pong + zout (layer 1).
// ---------------------------------------------------------------------------
template<bool ALLT>
__global__ void __launch_bounds__(256) gru_mma(
    const __half* __restrict__ WhhHi, const __half* __restrict__ WhhLo,
    const float* __restrict__ giAll, const float* __restrict__ bih,
    const float* __restrict__ bhh, __half* __restrict__ hB,
    float* __restrict__ zout, unsigned* cntArr, unsigned* genArr)
{
    extern __shared__ char smc[];
    __shared__ float sB[192];
    char* B_hh_hi = smc;
    char* B_hh_lo = smc + 48*1024;
    char* A1 = smc + 96*1024;

    const int tid = threadIdx.x, lane = tid & 31, w = tid >> 5;
    const int wM = w >> 2, wN = w & 3;
    const int m0 = blockIdx.x * 64, n0 = blockIdx.y * 32;
    const size_t PG = (size_t)Bsz * G3, PHB = (size_t)Bsz * Hsz;
    unsigned* cnt = cntArr + blockIdx.x * 8;
    volatile unsigned* gen = genArr + blockIdx.x * 8;

    fill_Bg(B_hh_hi, WhhHi, n0, tid);
    fill_Bg(B_hh_lo, WhhLo, n0, tid);
    if (tid < 192){
        int g = tid >> 5, c = tid & 31;
        sB[tid] = (g < 3) ? bih[g*Hsz + n0 + c] : bhh[(g-3)*Hsz + n0 + c];
    }

    const int cl = wN*8 + 2*(lane & 3);
    const int colb = n0 + cl;
    const int rloc = wM*32 + (lane >> 2);
    float h_own[2][2][2];
    #pragma unroll
    for (int m = 0; m < 2; m++)
        #pragma unroll
        for (int hr = 0; hr < 2; hr++){ h_own[m][hr][0] = 0.0f; h_own[m][hr][1] = 0.0f; }

    const unsigned gbase = *gen;
    __syncthreads();

    for (int t = 0; t < Tsz; t++){
        float accG[2][3][4];
        zero_acc(accG);
        float2 giv[2][2][3];

        if (t > 0){
            size_t rp = ALLT ? (size_t)(t-1) : (size_t)((t-1) & 1);
            fill_A(A1, hB + rp * PHB, m0, tid);
            __syncthreads();
            #pragma unroll
            for (int m = 0; m < 2; m++)
                #pragma unroll
                for (int hr = 0; hr < 2; hr++){
                    const float* gp = giAll + (size_t)t*PG
                        + (size_t)(m0 + rloc + m*16 + hr*8)*G3 + colb;
                    #pragma unroll
                    for (int g = 0; g < 3; g++)
                        giv[m][hr][g] = *reinterpret_cast<const float2*>(gp + g*256);
                }
            mma_multi<2,16,512,3>(A1, B_hh_hi, accG, B_hh_lo, accG,
                                  B_hh_hi, accG, B_hh_hi, accG, lane, wM, wN);
        } else {
            #pragma unroll
            for (int m = 0; m < 2; m++)
                #pragma unroll
                for (int hr = 0; hr < 2; hr++){
                    const float* gp = giAll + (size_t)(m0 + rloc + m*16 + hr*8)*G3 + colb;
                    #pragma unroll
                    for (int g = 0; g < 3; g++)
                        giv[m][hr][g] = *reinterpret_cast<const float2*>(gp + g*256);
                }
        }

        // ---- register-local epilogue ----
        {
            size_t wp = ALLT ? (size_t)t : (size_t)(t & 1);
            __half* hW = hB + wp * PHB;
            #pragma unroll
            for (int m = 0; m < 2; m++)
                #pragma unroll
                for (int hr = 0; hr < 2; hr++){
                    int row = m0 + rloc + m*16 + hr*8;
                    float hv2[2];
                    #pragma unroll
                    for (int cc = 0; cc < 2; cc++){
                        int q = hr*2 + cc;
                        float gr = (t > 0) ? accG[m][0][q] : 0.0f;
                        float gz = (t > 0) ? accG[m][1][q] : 0.0f;
                        float gn = (t > 0) ? accG[m][2][q] : 0.0f;
                        float gir = cc ? giv[m][hr][0].y : giv[m][hr][0].x;
                        float giz = cc ? giv[m][hr][1].y : giv[m][hr][1].x;
                        float gin = cc ? giv[m][hr][2].y : giv[m][hr][2].x;
                        float rg = sigmoidf_(gir + sB[cl+cc]      + gr + sB[96+cl+cc]);
                        float zg = sigmoidf_(giz + sB[32+cl+cc]   + gz + sB[128+cl+cc]);
                        float ng = tanhf_(gin + sB[64+cl+cc]      + rg*(gn + sB[160+cl+cc]));
                        float hv = (1.0f - zg)*ng + zg*h_own[m][hr][cc];
                        h_own[m][hr][cc] = hv;
                        hv2[cc] = hv;
                    }
                    __half2 hp;
                    hp.x = __float2half_rn(hv2[0]);
                    hp.y = __float2half_rn(hv2[1]);
                    *reinterpret_cast<u32*>(hW + (size_t)row*Hsz + colb) =
                        *reinterpret_cast<u32*>(&hp);
                    if (!ALLT && t == Tsz-1)
                        *reinterpret_cast<float2*>(zout + (size_t)row*Hsz + colb) =
                            make_float2(hv2[0], hv2[1]);
                }
        }

        grid_bar(cnt, gen, gbase + (unsigned)t + 1u, 7u);
    }
}

// ---------------------------------------------------------------------------
// Expert GEMM fp16 2-pass (proven R15)
// ---------------------------------------------------------------------------
template<int KDIM, bool EMIT_HALF>
__global__ void __launch_bounds__(256) gemm_expert(
    const __half* __restrict__ aH, size_t aExpStride,
    const __half* __restrict__ wHi, const __half* __restrict__ wLo,
    const float* __restrict__ bias, int N,
    float* __restrict__ outF, __half* __restrict__ outH)
{
    extern __shared__ char smc[];
    char* Asm = smc;
    char* Bh  = smc + 16*1024;
    char* Bl  = smc + 32*1024;

    const int tid = threadIdx.x, lane = tid & 31, w = tid >> 5;
    const int wM = w >> 2, wN = w & 3;
    const int e = blockIdx.z;
    const int n0 = blockIdx.x * 64, m0 = blockIdx.y * 64;
    const __half* Ap  = aH  + (size_t)e * aExpStride;
    const __half* Whp = wHi + (size_t)e * N * KDIM;
    const __half* Wlp = wLo + (size_t)e * N * KDIM;

    float acc[2][2][4];
    zero_acc(acc);

    for (int kc = 0; kc < KDIM; kc += 128){
        if (kc) __syncthreads();
        #pragma unroll
        for (int i = 0; i < 4; i++){
            int id = tid + i*256, r = id >> 4, c = id & 15;
            *reinterpret_cast<uint4*>(Asm + (size_t)r*256 + SWZ(r, c)) =
                *(reinterpret_cast<const uint4*>(Ap + (size_t)(m0+r)*KDIM + kc) + c);
            *reinterpret_cast<uint4*>(Bh + (size_t)r*256 + SWZ(r, c)) =
                *(reinterpret_cast<const uint4*>(Whp + (size_t)(n0+r)*KDIM + kc) + c);
            *reinterpret_cast<uint4*>(Bl + (size_t)r*256 + SWZ(r, c)) =
                *(reinterpret_cast<const uint4*>(Wlp + (size_t)(n0+r)*KDIM + kc) + c);
        }
        __syncthreads();
        mma_multi<2, 8, 256, 2>(Asm, Bh, acc, Bl, acc, Bh, acc, Bh, acc, lane, wM, wN);
    }

    const size_t ob = (size_t)e * Bsz * N;
    #pragma unroll
    for (int m = 0; m < 2; m++)
        #pragma unroll
        for (int f = 0; f < 2; f++){
            int r0 = m0 + wM*32 + m*16 + (lane >> 2);
            int c0 = n0 + wN*16 + f*8 + 2*(lane & 3);
            float b0v = bias[e*N + c0], b1v = bias[e*N + c0 + 1];
            #pragma unroll
            for (int hrow = 0; hrow < 2; hrow++){
                int r = r0 + hrow*8;
                float v0 = fmaxf(acc[m][f][hrow*2+0] + b0v, 0.0f);
                float v1 = fmaxf(acc[m][f][hrow*2+1] + b1v, 0.0f);
                if constexpr (EMIT_HALF){
                    __half2 hp;
                    hp.x = __float2half_rn(v0);
                    hp.y = __float2half_rn(v1);
                    *reinterpret_cast<u32*>(outH + ob + (size_t)r*N + c0) =
                        *reinterpret_cast<u32*>(&hp);
                } else {
                    *reinterpret_cast<float2*>(outF + ob + (size_t)r*N + c0) = make_float2(v0, v1);
                }
            }
        }
}

// ---------------- q / combine (proven) ----------------
__global__ void __launch_bounds__(256) qkernel(
    const float* __restrict__ z, const float* __restrict__ cent, float* __restrict__ q)
{
    int warp = threadIdx.x >> 5, lane = threadIdx.x & 31;
    int b = blockIdx.x*8 + warp;
    float zr[8];
    #pragma unroll
    for (int i = 0; i < 8; i++) zr[i] = z[(size_t)b*Hsz + lane + 32*i];
    float s = 0.0f;
    for (int k = 0; k < Ksz; k++){
        float d = 0.0f;
        #pragma unroll
        for (int i = 0; i < 8; i++){
            float t = zr[i] - cent[k*Hsz + lane + 32*i];
            d = fmaf(t, t, d);
        }
        #pragma unroll
        for (int off = 16; off; off >>= 1) d += __shfl_xor_sync(0xffffffffu, d, off);
        if (lane == k) s = 1.0f / (1.0f + d);
    }
    float tot = s;
    #pragma unroll
    for (int off = 16; off; off >>= 1) tot += __shfl_xor_sync(0xffffffffu, tot, off);
    if (lane < Ksz) q[(size_t)b*Ksz + lane] = s / tot;
}

__global__ void __launch_bounds__(256) combine_kernel(
    const float* __restrict__ h2, const float* __restrict__ q,
    const float* __restrict__ eW3, const float* __restrict__ eb3, float* __restrict__ out)
{
    int warp = threadIdx.x >> 5, lane = threadIdx.x & 31;
    int b = blockIdx.x*8 + warp;
    float acc[Ksz][2];
    #pragma unroll
    for (int k = 0; k < Ksz; k++){ acc[k][0] = 0.0f; acc[k][1] = 0.0f; }
    for (int f = lane; f < E2sz; f += 32){
        #pragma unroll
        for (int k = 0; k < Ksz; k++){
            float hv = h2[((size_t)k*Bsz + b)*E2sz + f];
            acc[k][0] = fmaf(hv, eW3[(size_t)(k*2+0)*E2sz + f], acc[k][0]);
            acc[k][1] = fmaf(hv, eW3[(size_t)(k*2+1)*E2sz + f], acc[k][1]);
        }
    }
    #pragma unroll
    for (int k = 0; k < Ksz; k++)
        #pragma unroll
        for (int c = 0; c < 2; c++)
            #pragma unroll
            for (int off = 16; off; off >>= 1)
                acc[k][c] += __shfl_xor_sync(0xffffffffu, acc[k][c], off);
    if (lane == 0){
        float p0 = 0.0f, p1 = 0.0f;
        #pragma unroll
        for (int k = 0; k < Ksz; k++){
            float qq = q[(size_t)b*Ksz + k];
            p0 = fmaf(qq, acc[k][0] + eb3[k*2+0], p0);
            p1 = fmaf(qq, acc[k][1] + eb3[k*2+1], p1);
        }
        out[b*2+0] = p0; out[b*2+1] = p1;
    }
}

// ---------------------------------------------------------------------------
#define MMA_SMEM   ((96 + 32) * 1024)
#define GI0_SMEM   (64 * 1024)
#define GI1_SMEM   (128 * 1024)
#define EXP_SMEM   (48 * 1024)

extern "C" void kernel_launch(void* const* d_in, const int* in_sizes, int n_in,
                              void* d_out, int out_size)
{
    const float* x    = (const float*)d_in[0];
    const float* Wih0 = (const float*)d_in[1];
    const float* Whh0 = (const float*)d_in[2];
    const float* bih0 = (const float*)d_in[3];
    const float* bhh0 = (const float*)d_in[4];
    const float* Wih1 = (const float*)d_in[5];
    const float* Whh1 = (const float*)d_in[6];
    const float* bih1 = (const float*)d_in[7];
    const float* bhh1 = (const float*)d_in[8];
    const float* cent = (const float*)d_in[9];
    const float* eW1  = (const float*)d_in[10];
    const float* eb1  = (const float*)d_in[11];
    const float* eW2  = (const float*)d_in[12];
    const float* eb2  = (const float*)d_in[13];
    const float* eW3  = (const float*)d_in[14];
    const float* eb3  = (const float*)d_in[15];
    float* out = (float*)d_out;

    float *gi0, *gi1, *z, *qb, *e2;
    __half *xH, *wihH0, *whhH0, *wihH1, *whhH1, *hAll, *hH1, *eW1H, *eW2H, *e1H;
    unsigned *cnt0, *gen0, *cnt1, *gen1;
    cudaGetSymbolAddress((void**)&gi0,   g_gi0);
    cudaGetSymbolAddress((void**)&gi1,   g_gi1);
    cudaGetSymbolAddress((void**)&xH,    g_xH);
    cudaGetSymbolAddress((void**)&wihH0, g_WihH0);
    cudaGetSymbolAddress((void**)&whhH0, g_WhhH0);
    cudaGetSymbolAddress((void**)&wihH1, g_WihH1);
    cudaGetSymbolAddress((void**)&whhH1, g_WhhH1);
    cudaGetSymbolAddress((void**)&hAll,  g_hAll);
    cudaGetSymbolAddress((void**)&hH1,   g_hH1);
    cudaGetSymbolAddress((void**)&eW1H,  g_eW1H);
    cudaGetSymbolAddress((void**)&eW2H,  g_eW2H);
    cudaGetSymbolAddress((void**)&e1H,   g_e1H);
    cudaGetSymbolAddress((void**)&z,     g_z);
    cudaGetSymbolAddress((void**)&qb,    g_q);
    cudaGetSymbolAddress((void**)&e2,    g_e2);
    cudaGetSymbolAddress((void**)&cnt0,  g_cnt0);
    cudaGetSymbolAddress((void**)&gen0,  g_gen0);
    cudaGetSymbolAddress((void**)&cnt1,  g_cnt1);
    cudaGetSymbolAddress((void**)&gen1,  g_gen1);

    cudaFuncSetAttribute(gru_mma<true>,
                         cudaFuncAttributeMaxDynamicSharedMemorySize, MMA_SMEM);
    cudaFuncSetAttribute(gru_mma<false>,
                         cudaFuncAttributeMaxDynamicSharedMemorySize, MMA_SMEM);
    cudaFuncSetAttribute(gi0_mma,
                         cudaFuncAttributeMaxDynamicSharedMemorySize, GI0_SMEM);
    cudaFuncSetAttribute(gi1_mma,
                         cudaFuncAttributeMaxDynamicSharedMemorySize, GI1_SMEM);
    cudaFuncSetAttribute(gemm_expert<256, true>,
                         cudaFuncAttributeMaxDynamicSharedMemorySize, EXP_SMEM);
    cudaFuncSetAttribute(gemm_expert<512, false>,
                         cudaFuncAttributeMaxDynamicSharedMemorySize, EXP_SMEM);

    const size_t WN  = (size_t)G3 * Hsz;
    const size_t WN0 = (size_t)G3 * Isz;
    const size_t XN  = (size_t)MT * Isz;
    const size_t W1N = (size_t)Ksz * E1sz * Hsz;
    const size_t W2N = (size_t)Ksz * E2sz * E1sz;
    const size_t PHB = (size_t)Bsz * Hsz;

    cvt_h<<<(int)(XN/256), 256>>>(x, xH, (int)XN);
    cvt_split<<<(int)((WN0+255)/256), 256>>>(Wih0, wihH0, wihH0 + WN0, (int)WN0);
    cvt_split<<<(int)(WN/256), 256>>>(Whh0, whhH0, whhH0 + WN, (int)WN);
    cvt_split<<<(int)(WN/256), 256>>>(Wih1, wihH1, wihH1 + WN, (int)WN);
    cvt_split<<<(int)(WN/256), 256>>>(Whh1, whhH1, whhH1 + WN, (int)WN);
    cvt_split<<<(int)(W1N/256), 256>>>(eW1, eW1H, eW1H + W1N, (int)W1N);
    cvt_split<<<(int)(W2N/256), 256>>>(eW2, eW2H, eW2H + W2N, (int)W2N);

    gi0_mma<<<dim3(8, MT/64), 256, GI0_SMEM>>>(xH, wihH0, wihH0 + WN0, gi0);

    // layer 0 chain (2 passes/step; stores h[t] for all t)
    gru_mma<true><<<dim3(16, 8), 256, MMA_SMEM>>>(
        whhH0, whhH0 + WN, gi0, bih0, bhh0, hAll, nullptr, cnt0, gen0);

    // gi1 = hAll @ Wih1^T (parallel, tensor)
    gi1_mma<<<dim3(8, MT/64), 256, GI1_SMEM>>>(hAll, wihH1, wihH1 + WN, gi1);

    // layer 1 chain
    gru_mma<false><<<dim3(16, 8), 256, MMA_SMEM>>>(
        whhH1, whhH1 + WN, gi1, bih1, bhh1, hH1, z, cnt1, gen1);

    qkernel<<<128, 256>>>(z, cent, qb);
    // z fp16 = hH1 plane (127 & 1) = 1
    gemm_expert<256, true><<<dim3(8, 16, 8), 256, EXP_SMEM>>>(
        hH1 + PHB, (size_t)0, eW1H, eW1H + W1N, eb1, E1sz,
        nullptr, e1H);
    gemm_expert<512, false><<<dim3(4, 16, 8), 256, EXP_SMEM>>>(
        e1H, (size_t)Bsz*E1sz, eW2H, eW2H + W2N, eb2, E2sz,
        e2, nullptr);
    combine_kernel<<<128, 256>>>(e2, qb, eW3, eb3, out);

    (void)in_sizes; (void)n_in; (void)out_size;
}